// round 5
// baseline (speedup 1.0000x reference)
#include <cuda_runtime.h>
#include <cuda_fp16.h>
#include <cstdint>

#define B_DIM 8
#define T_DIM 2048
#define D_DIM 2048
#define M_DIM (B_DIM * T_DIM)   // 16384

// ---------------- device-global scratch (static, allowed) -------------------
__device__ __align__(256) __half g_Ph[(size_t)M_DIM * D_DIM];  // (x@Wp^T+bp)/6, fp16
__device__ __align__(256) __half g_A [(size_t)M_DIM * D_DIM];  // fp16(x)
__device__ __align__(256) __half g_B [(size_t)D_DIM * D_DIM];  // fp16(Wp)

// ---------------- helpers ----------------------------------------------------
__device__ __forceinline__ uint32_t smem_u32(const void* p) {
    uint32_t a;
    asm("{ .reg .u64 t; cvta.to.shared.u64 t, %1; cvt.u32.u64 %0, t; }" : "=r"(a) : "l"(p));
    return a;
}
__device__ __forceinline__ void cp16(uint32_t sdst, const void* gsrc) {
    asm volatile("cp.async.cg.shared.global [%0], [%1], 16;" :: "r"(sdst), "l"(gsrc));
}
__device__ __forceinline__ uint32_t sw128(uint32_t o) { return o ^ ((o >> 3) & 0x70); }

__device__ __forceinline__ void ldmatrix_x4(uint32_t* f, uint32_t addr) {
    asm volatile("ldmatrix.sync.aligned.m8n8.x4.shared.b16 {%0,%1,%2,%3}, [%4];"
                 : "=r"(f[0]), "=r"(f[1]), "=r"(f[2]), "=r"(f[3]) : "r"(addr));
}
__device__ __forceinline__ void mma16816(float* c, const uint32_t* a,
                                         uint32_t b0, uint32_t b1) {
    asm volatile(
        "mma.sync.aligned.m16n8k16.row.col.f32.f16.f16.f32 "
        "{%0,%1,%2,%3}, {%4,%5,%6,%7}, {%8,%9}, {%0,%1,%2,%3};"
        : "+f"(c[0]), "+f"(c[1]), "+f"(c[2]), "+f"(c[3])
        : "r"(a[0]), "r"(a[1]), "r"(a[2]), "r"(a[3]), "r"(b0), "r"(b1));
}

// ---------------- fp32 -> fp16 convert ---------------------------------------
__global__ __launch_bounds__(256) void cvt_fp16_kernel(
    const float4* __restrict__ src, uint2* __restrict__ dst, int n4) {
    int i = blockIdx.x * 256 + threadIdx.x;
    if (i >= n4) return;
    float4 v = src[i];
    __half2 h0 = __floats2half2_rn(v.x, v.y);
    __half2 h1 = __floats2half2_rn(v.z, v.w);
    dst[i] = make_uint2(*reinterpret_cast<uint32_t*>(&h0),
                        *reinterpret_cast<uint32_t*>(&h1));
}

// ---------------- HMMA GEMM: g_Ph = fp16((A @ B^T + bp) / 6) -----------------
// CTA tile 128x256, BK=64, 8 warps as 2(M) x 4(N) => 64x64 warp tile.
// 4-stage cp.async pipeline. A,B row-major [rows, K] fp16, SW128 smem.
namespace hg {
constexpr int BM = 128, BN = 256, BK = 64, STAGES = 4;
constexpr int NKT = D_DIM / BK;                 // 32
constexpr int TILE_A = BM * 128;                // 16 KB
constexpr int TILE_B = BN * 128;                // 32 KB
constexpr int SMEM_BYTES = STAGES * (TILE_A + TILE_B) + 1024;  // 197632
}

__global__ __launch_bounds__(256, 1) void gemm_hmma_kernel(const float* __restrict__ bias) {
    using namespace hg;
    extern __shared__ char smem_raw[];
    const uint32_t sbase = (smem_u32(smem_raw) + 1023u) & ~1023u;
    const uint32_t bbase = sbase + STAGES * TILE_A;

    const int tid  = threadIdx.x;
    const int wid  = tid >> 5;
    const int lane = tid & 31;
    const int brow = blockIdx.y * BM;
    const int bcol = blockIdx.x * BN;
    const int wm = wid & 1;      // 2 warp rows  -> 64 M-rows each
    const int wn = wid >> 1;     // 4 warp cols  -> 64 N-cols each

    const __half* Ag = g_A + (size_t)brow * D_DIM;
    const __half* Bg = g_B + (size_t)bcol * D_DIM;

    const int lrow = tid >> 3;   // 0..31
    const int lseg = tid & 7;    // 16B segment

    auto load_stage = [&](int s, int k0) {
        const uint32_t a_s = sbase + s * TILE_A;
        const uint32_t b_s = bbase + s * TILE_B;
#pragma unroll
        for (int p = 0; p < 4; p++) {   // A: 128 rows
            const int row = lrow + p * 32;
            cp16(a_s + sw128((uint32_t)(row * 128 + lseg * 16)),
                 Ag + (size_t)row * D_DIM + k0 + lseg * 8);
        }
#pragma unroll
        for (int p = 0; p < 8; p++) {   // B: 256 rows
            const int row = lrow + p * 32;
            cp16(b_s + sw128((uint32_t)(row * 128 + lseg * 16)),
                 Bg + (size_t)row * D_DIM + k0 + lseg * 8);
        }
    };

    float acc[4][8][4];
#pragma unroll
    for (int i = 0; i < 4; i++)
#pragma unroll
        for (int j = 0; j < 8; j++)
#pragma unroll
            for (int e = 0; e < 4; e++) acc[i][j][e] = 0.0f;

#pragma unroll
    for (int s = 0; s < STAGES - 1; s++) {
        load_stage(s, s * BK);
        asm volatile("cp.async.commit_group;" ::: "memory");
    }

    const int a_r_base = wm * 64 + (lane & 15);
    const int ab_cb    = ((lane >> 4) << 4);   // 0 or 16 bytes
    const int b_r_base = wn * 64 + (lane & 7) + ((lane >> 3) & 1) * 8;

#pragma unroll 1
    for (int kt = 0; kt < NKT; kt++) {
        asm volatile("cp.async.wait_group 2;" ::: "memory");
        __syncthreads();

        const int pf = kt + STAGES - 1;
        if (pf < NKT) load_stage(pf % STAGES, pf * BK);
        asm volatile("cp.async.commit_group;" ::: "memory");

        const int s = kt % STAGES;
        const uint32_t a_s = sbase + s * TILE_A;
        const uint32_t b_s = bbase + s * TILE_B;

#pragma unroll
        for (int kk = 0; kk < BK / 16; kk++) {
            const int kb = kk * 32;   // bytes
            uint32_t af[4][4];
#pragma unroll
            for (int i = 0; i < 4; i++) {
                const int r = a_r_base + i * 16;
                ldmatrix_x4(af[i], a_s + sw128((uint32_t)(r * 128 + kb + ab_cb)));
            }
            uint32_t bf[4][4];
#pragma unroll
            for (int j = 0; j < 4; j++) {
                const int r = b_r_base + j * 16;
                ldmatrix_x4(bf[j], b_s + sw128((uint32_t)(r * 128 + kb + ab_cb)));
            }
#pragma unroll
            for (int i = 0; i < 4; i++)
#pragma unroll
                for (int j = 0; j < 4; j++) {
                    mma16816(acc[i][2 * j],     af[i], bf[j][0], bf[j][2]);
                    mma16816(acc[i][2 * j + 1], af[i], bf[j][1], bf[j][3]);
                }
        }
    }

    // epilogue: fp16 store of (acc + bias) / 6
    const float inv6 = 1.0f / 6.0f;
    const int prow0 = brow + wm * 64 + (lane >> 2);
    const int pcol0 = bcol + wn * 64 + (lane & 3) * 2;
#pragma unroll
    for (int i = 0; i < 4; i++) {
        const size_t r0 = (size_t)(prow0 + i * 16);
#pragma unroll
        for (int j = 0; j < 8; j++) {
            const int c = pcol0 + j * 8;
            const float b0 = bias[c], b1 = bias[c + 1];
            __half2 lo = __floats2half2_rn((acc[i][j][0] + b0) * inv6,
                                           (acc[i][j][1] + b1) * inv6);
            __half2 hi = __floats2half2_rn((acc[i][j][2] + b0) * inv6,
                                           (acc[i][j][3] + b1) * inv6);
            *reinterpret_cast<__half2*>(&g_Ph[r0 * D_DIM + c])       = lo;
            *reinterpret_cast<__half2*>(&g_Ph[(r0 + 8) * D_DIM + c]) = hi;
        }
    }
}

// ---------------- fused chained LayerNorm (vectorized, P in fp16) ------------
__device__ __forceinline__ float2 block_sum2(float a, float b) {
    __shared__ float sm[16];
    const int lane = threadIdx.x & 31;
    const int wid  = threadIdx.x >> 5;
#pragma unroll
    for (int o = 16; o > 0; o >>= 1) {
        a += __shfl_xor_sync(0xffffffffu, a, o);
        b += __shfl_xor_sync(0xffffffffu, b, o);
    }
    __syncthreads();
    if (lane == 0) { sm[wid] = a; sm[8 + wid] = b; }
    __syncthreads();
    float sa = 0.0f, sb = 0.0f;
#pragma unroll
    for (int i = 0; i < 8; i++) { sa += sm[i]; sb += sm[8 + i]; }
    return make_float2(sa, sb);
}

__global__ __launch_bounds__(256) void ln_fuse_kernel(
    const float* __restrict__ x, const float* __restrict__ gamma,
    const float* __restrict__ beta, float* __restrict__ out) {
    const int r   = blockIdx.x;
    const int t   = r & (T_DIM - 1);
    const int tid = threadIdx.x;
    const float invD = 1.0f / (float)D_DIM;
    constexpr int DP = D_DIM / 2;   // pairs per row

    const float2*  xr = (const float2*)x + (size_t)r * DP;
    const int p1row   = (t == 0) ? (r + 1) : (r - 1);
    const __half2* p1 = (const __half2*)g_Ph + (size_t)p1row * DP;
    const float2*  g2 = (const float2*)gamma;
    const float2*  b2 = (const float2*)beta;

    float2 v[4];
    float s = 0.0f, sq = 0.0f;
#pragma unroll
    for (int i = 0; i < 4; i++) {
        const int q = i * 256 + tid;
        const float2 xv = xr[q];
        const float2 pv = __half22float2(p1[q]);
        const float a = xv.x + pv.x, b = xv.y + pv.y;
        v[i] = make_float2(a, b);
        s += a + b; sq += a * a + b * b;
    }
    float2 red = block_sum2(s, sq);
    float mean = red.x * invD;
    float var  = red.y * invD - mean * mean;
    float rstd = rsqrtf(var + 1e-5f);

    if (t >= 1 && t <= T_DIM - 2) {
        const __half2* p2 = (const __half2*)g_Ph + (size_t)(r + 1) * DP;
        s = 0.0f; sq = 0.0f;
#pragma unroll
        for (int i = 0; i < 4; i++) {
            const int q = i * 256 + tid;
            const float2 gg = g2[q], bb = b2[q];
            const float2 pv = __half22float2(p2[q]);
            const float a = (v[i].x - mean) * rstd * gg.x + bb.x + pv.x;
            const float b = (v[i].y - mean) * rstd * gg.y + bb.y + pv.y;
            v[i] = make_float2(a, b);
            s += a + b; sq += a * a + b * b;
        }
        red  = block_sum2(s, sq);
        mean = red.x * invD;
        var  = red.y * invD - mean * mean;
        rstd = rsqrtf(var + 1e-5f);
    }

    float2* orow = (float2*)out + (size_t)r * DP;
#pragma unroll
    for (int i = 0; i < 4; i++) {
        const int q = i * 256 + tid;
        const float2 gg = g2[q], bb = b2[q];
        orow[q] = make_float2((v[i].x - mean) * rstd * gg.x + bb.x,
                              (v[i].y - mean) * rstd * gg.y + bb.y);
    }
}

// ---------------- launch ------------------------------------------------------
extern "C" void kernel_launch(void* const* d_in, const int* in_sizes, int n_in,
                              void* d_out, int out_size) {
    const float* x     = (const float*)d_in[0];
    const float* Wp    = (const float*)d_in[5];
    const float* bp    = (const float*)d_in[6];
    const float* gamma = (const float*)d_in[7];
    const float* beta  = (const float*)d_in[8];
    float* out = (float*)d_out;

    static bool attr_set = false;
    if (!attr_set) {
        cudaFuncSetAttribute(gemm_hmma_kernel,
                             cudaFuncAttributeMaxDynamicSharedMemorySize, hg::SMEM_BYTES);
        attr_set = true;
    }

    __half* gA; cudaGetSymbolAddress((void**)&gA, g_A);
    __half* gB; cudaGetSymbolAddress((void**)&gB, g_B);

    const int nx4 = M_DIM * D_DIM / 4;
    const int nw4 = D_DIM * D_DIM / 4;
    cvt_fp16_kernel<<<nx4 / 256, 256>>>((const float4*)x,  (uint2*)gA, nx4);
    cvt_fp16_kernel<<<nw4 / 256, 256>>>((const float4*)Wp, (uint2*)gB, nw4);

    dim3 ggrid(D_DIM / hg::BN, M_DIM / hg::BM);   // (8, 128)
    gemm_hmma_kernel<<<ggrid, 256, hg::SMEM_BYTES>>>(bp);

    ln_fuse_kernel<<<M_DIM, 256>>>(x, gamma, beta, out);
}

// round 7
// speedup vs baseline: 1.0415x; 1.0415x over previous
#include <cuda_runtime.h>
#include <cuda_fp16.h>
#include <cstdint>

#define B_DIM 8
#define T_DIM 2048
#define D_DIM 2048
#define M_DIM (B_DIM * T_DIM)   // 16384

// ---------------- device-global scratch (static, allowed) -------------------
__device__ __align__(256) __half g_Ph[(size_t)M_DIM * D_DIM];  // (x@Wp^T+bp)/6, fp16
__device__ __align__(256) __half g_A [(size_t)M_DIM * D_DIM];  // fp16(x)
__device__ __align__(256) __half g_B [(size_t)D_DIM * D_DIM];  // fp16(Wp)

// ---------------- helpers ----------------------------------------------------
__device__ __forceinline__ uint32_t smem_u32(const void* p) {
    uint32_t a;
    asm("{ .reg .u64 t; cvta.to.shared.u64 t, %1; cvt.u32.u64 %0, t; }" : "=r"(a) : "l"(p));
    return a;
}
__device__ __forceinline__ void cp16(uint32_t sdst, const void* gsrc) {
    asm volatile("cp.async.cg.shared.global [%0], [%1], 16;" :: "r"(sdst), "l"(gsrc));
}
__device__ __forceinline__ uint32_t sw128(uint32_t o) { return o ^ ((o >> 3) & 0x70); }

__device__ __forceinline__ void ldmatrix_x4(uint32_t* f, uint32_t addr) {
    asm volatile("ldmatrix.sync.aligned.m8n8.x4.shared.b16 {%0,%1,%2,%3}, [%4];"
                 : "=r"(f[0]), "=r"(f[1]), "=r"(f[2]), "=r"(f[3]) : "r"(addr));
}
__device__ __forceinline__ void mma16816(float* c, const uint32_t* a,
                                         uint32_t b0, uint32_t b1) {
    asm volatile(
        "mma.sync.aligned.m16n8k16.row.col.f32.f16.f16.f32 "
        "{%0,%1,%2,%3}, {%4,%5,%6,%7}, {%8,%9}, {%0,%1,%2,%3};"
        : "+f"(c[0]), "+f"(c[1]), "+f"(c[2]), "+f"(c[3])
        : "r"(a[0]), "r"(a[1]), "r"(a[2]), "r"(a[3]), "r"(b0), "r"(b1));
}

// ---------------- fp32 -> fp16 convert ---------------------------------------
__global__ __launch_bounds__(256) void cvt_fp16_kernel(
    const float4* __restrict__ src, uint2* __restrict__ dst, int n4) {
    int i = blockIdx.x * 256 + threadIdx.x;
    if (i >= n4) return;
    float4 v = src[i];
    __half2 h0 = __floats2half2_rn(v.x, v.y);
    __half2 h1 = __floats2half2_rn(v.z, v.w);
    dst[i] = make_uint2(*reinterpret_cast<uint32_t*>(&h0),
                        *reinterpret_cast<uint32_t*>(&h1));
}

// ---------------- HMMA GEMM: g_Ph = fp16((A @ B^T + bp) / 6) -----------------
// CTA tile 128x128, 128 threads (4 warps, 2x2) => 64x64 warp tile.
// BK=64, 3-stage cp.async pipeline, 96KB smem -> 2 CTAs/SM.
namespace hg {
constexpr int BM = 128, BN = 128, BK = 64, STAGES = 3;
constexpr int NKT = D_DIM / BK;                 // 32
constexpr int TILE_A = BM * 128;                // 16 KB
constexpr int TILE_B = BN * 128;                // 16 KB
constexpr int SMEM_BYTES = STAGES * (TILE_A + TILE_B) + 1024;  // 99328
}

__global__ __launch_bounds__(128, 2) void gemm_hmma_kernel(const float* __restrict__ bias) {
    using namespace hg;
    extern __shared__ char smem_raw[];
    const uint32_t sbase = (smem_u32(smem_raw) + 1023u) & ~1023u;
    const uint32_t bbase = sbase + STAGES * TILE_A;

    const int tid  = threadIdx.x;
    const int wid  = tid >> 5;
    const int lane = tid & 31;
    const int brow = blockIdx.y * BM;
    const int bcol = blockIdx.x * BN;
    const int wm = wid & 1;      // 2 warp rows -> 64 M-rows each
    const int wn = wid >> 1;     // 2 warp cols -> 64 N-cols each

    const __half* Ag = g_A + (size_t)brow * D_DIM;
    const __half* Bg = g_B + (size_t)bcol * D_DIM;

    const int lrow = tid >> 3;   // 0..15
    const int lseg = tid & 7;    // 16B segment

    auto load_stage = [&](int s, int k0) {
        const uint32_t a_s = sbase + s * TILE_A;
        const uint32_t b_s = bbase + s * TILE_B;
#pragma unroll
        for (int p = 0; p < 8; p++) {   // 128 rows, 16 rows per pass
            const int row = lrow + p * 16;
            const uint32_t off = sw128((uint32_t)(row * 128 + lseg * 16));
            const size_t gofs = (size_t)row * D_DIM + k0 + lseg * 8;
            cp16(a_s + off, Ag + gofs);
            cp16(b_s + off, Bg + gofs);
        }
    };

    float acc[4][8][4];
#pragma unroll
    for (int i = 0; i < 4; i++)
#pragma unroll
        for (int j = 0; j < 8; j++)
#pragma unroll
            for (int e = 0; e < 4; e++) acc[i][j][e] = 0.0f;

#pragma unroll
    for (int s = 0; s < STAGES - 1; s++) {
        load_stage(s, s * BK);
        asm volatile("cp.async.commit_group;" ::: "memory");
    }

    const int a_r_base = wm * 64 + (lane & 15);
    const int ab_cb    = ((lane >> 4) << 4);   // 0 or 16 bytes
    const int b_r_base = wn * 64 + (lane & 7) + ((lane >> 3) & 1) * 8;

#pragma unroll 1
    for (int kt = 0; kt < NKT; kt++) {
        asm volatile("cp.async.wait_group 1;" ::: "memory");
        __syncthreads();

        const int pf = kt + STAGES - 1;
        if (pf < NKT) load_stage(pf % STAGES, pf * BK);
        asm volatile("cp.async.commit_group;" ::: "memory");

        const int s = kt % STAGES;
        const uint32_t a_s = sbase + s * TILE_A;
        const uint32_t b_s = bbase + s * TILE_B;

#pragma unroll
        for (int kk = 0; kk < BK / 16; kk++) {
            const int kb = kk * 32;   // bytes
            uint32_t af[4][4];
#pragma unroll
            for (int i = 0; i < 4; i++) {
                const int r = a_r_base + i * 16;
                ldmatrix_x4(af[i], a_s + sw128((uint32_t)(r * 128 + kb + ab_cb)));
            }
            uint32_t bf[4][4];
#pragma unroll
            for (int j = 0; j < 4; j++) {
                const int r = b_r_base + j * 16;
                ldmatrix_x4(bf[j], b_s + sw128((uint32_t)(r * 128 + kb + ab_cb)));
            }
#pragma unroll
            for (int i = 0; i < 4; i++)
#pragma unroll
                for (int j = 0; j < 4; j++) {
                    mma16816(acc[i][2 * j],     af[i], bf[j][0], bf[j][2]);
                    mma16816(acc[i][2 * j + 1], af[i], bf[j][1], bf[j][3]);
                }
        }
    }

    // epilogue: fp16 store of (acc + bias) / 6
    const float inv6 = 1.0f / 6.0f;
    const int prow0 = brow + wm * 64 + (lane >> 2);
    const int pcol0 = bcol + wn * 64 + (lane & 3) * 2;
#pragma unroll
    for (int i = 0; i < 4; i++) {
        const size_t r0 = (size_t)(prow0 + i * 16);
#pragma unroll
        for (int j = 0; j < 8; j++) {
            const int c = pcol0 + j * 8;
            const float b0 = bias[c], b1 = bias[c + 1];
            __half2 lo = __floats2half2_rn((acc[i][j][0] + b0) * inv6,
                                           (acc[i][j][1] + b1) * inv6);
            __half2 hi = __floats2half2_rn((acc[i][j][2] + b0) * inv6,
                                           (acc[i][j][3] + b1) * inv6);
            *reinterpret_cast<__half2*>(&g_Ph[r0 * D_DIM + c])       = lo;
            *reinterpret_cast<__half2*>(&g_Ph[(r0 + 8) * D_DIM + c]) = hi;
        }
    }
}

// ---------------- fused chained LayerNorm (vectorized, P in fp16) ------------
__device__ __forceinline__ float2 block_sum2(float a, float b) {
    __shared__ float sm[16];
    const int lane = threadIdx.x & 31;
    const int wid  = threadIdx.x >> 5;
#pragma unroll
    for (int o = 16; o > 0; o >>= 1) {
        a += __shfl_xor_sync(0xffffffffu, a, o);
        b += __shfl_xor_sync(0xffffffffu, b, o);
    }
    __syncthreads();
    if (lane == 0) { sm[wid] = a; sm[8 + wid] = b; }
    __syncthreads();
    float sa = 0.0f, sb = 0.0f;
#pragma unroll
    for (int i = 0; i < 8; i++) { sa += sm[i]; sb += sm[8 + i]; }
    return make_float2(sa, sb);
}

__global__ __launch_bounds__(256) void ln_fuse_kernel(
    const float* __restrict__ x, const float* __restrict__ gamma,
    const float* __restrict__ beta, float* __restrict__ out) {
    const int r   = blockIdx.x;
    const int t   = r & (T_DIM - 1);
    const int tid = threadIdx.x;
    const float invD = 1.0f / (float)D_DIM;
    constexpr int DP = D_DIM / 2;   // pairs per row

    const float2*  xr = (const float2*)x + (size_t)r * DP;
    const int p1row   = (t == 0) ? (r + 1) : (r - 1);
    const __half2* p1 = (const __half2*)g_Ph + (size_t)p1row * DP;
    const float2*  g2 = (const float2*)gamma;
    const float2*  b2 = (const float2*)beta;

    float2 v[4];
    float s = 0.0f, sq = 0.0f;
#pragma unroll
    for (int i = 0; i < 4; i++) {
        const int q = i * 256 + tid;
        const float2 xv = xr[q];
        const float2 pv = __half22float2(p1[q]);
        const float a = xv.x + pv.x, b = xv.y + pv.y;
        v[i] = make_float2(a, b);
        s += a + b; sq += a * a + b * b;
    }
    float2 red = block_sum2(s, sq);
    float mean = red.x * invD;
    float var  = red.y * invD - mean * mean;
    float rstd = rsqrtf(var + 1e-5f);

    if (t >= 1 && t <= T_DIM - 2) {
        const __half2* p2 = (const __half2*)g_Ph + (size_t)(r + 1) * DP;
        s = 0.0f; sq = 0.0f;
#pragma unroll
        for (int i = 0; i < 4; i++) {
            const int q = i * 256 + tid;
            const float2 gg = g2[q], bb = b2[q];
            const float2 pv = __half22float2(p2[q]);
            const float a = (v[i].x - mean) * rstd * gg.x + bb.x + pv.x;
            const float b = (v[i].y - mean) * rstd * gg.y + bb.y + pv.y;
            v[i] = make_float2(a, b);
            s += a + b; sq += a * a + b * b;
        }
        red  = block_sum2(s, sq);
        mean = red.x * invD;
        var  = red.y * invD - mean * mean;
        rstd = rsqrtf(var + 1e-5f);
    }

    float2* orow = (float2*)out + (size_t)r * DP;
#pragma unroll
    for (int i = 0; i < 4; i++) {
        const int q = i * 256 + tid;
        const float2 gg = g2[q], bb = b2[q];
        orow[q] = make_float2((v[i].x - mean) * rstd * gg.x + bb.x,
                              (v[i].y - mean) * rstd * gg.y + bb.y);
    }
}

// ---------------- launch ------------------------------------------------------
extern "C" void kernel_launch(void* const* d_in, const int* in_sizes, int n_in,
                              void* d_out, int out_size) {
    const float* x     = (const float*)d_in[0];
    const float* Wp    = (const float*)d_in[5];
    const float* bp    = (const float*)d_in[6];
    const float* gamma = (const float*)d_in[7];
    const float* beta  = (const float*)d_in[8];
    float* out = (float*)d_out;

    static bool attr_set = false;
    if (!attr_set) {
        cudaFuncSetAttribute(gemm_hmma_kernel,
                             cudaFuncAttributeMaxDynamicSharedMemorySize, hg::SMEM_BYTES);
        attr_set = true;
    }

    __half* gA; cudaGetSymbolAddress((void**)&gA, g_A);
    __half* gB; cudaGetSymbolAddress((void**)&gB, g_B);

    const int nx4 = M_DIM * D_DIM / 4;
    const int nw4 = D_DIM * D_DIM / 4;
    cvt_fp16_kernel<<<nx4 / 256, 256>>>((const float4*)x,  (uint2*)gA, nx4);
    cvt_fp16_kernel<<<nw4 / 256, 256>>>((const float4*)Wp, (uint2*)gB, nw4);

    dim3 ggrid(D_DIM / hg::BN, M_DIM / hg::BM);   // (16, 128)
    gemm_hmma_kernel<<<ggrid, 128, hg::SMEM_BYTES>>>(bp);

    ln_fuse_kernel<<<M_DIM, 256>>>(x, gamma, beta, out);
}

// round 8
// speedup vs baseline: 1.1747x; 1.1280x over previous
#include <cuda_runtime.h>
#include <cuda_fp16.h>
#include <cstdint>

#define B_DIM 8
#define T_DIM 2048
#define D_DIM 2048
#define M_DIM (B_DIM * T_DIM)   // 16384

// ---------------- device-global scratch (static, allowed) -------------------
__device__ __align__(256) __half g_Ph[(size_t)M_DIM * D_DIM];  // (x@Wp^T+bp)/6, fp16
__device__ __align__(256) __half g_A [(size_t)M_DIM * D_DIM];  // fp16(x)
__device__ __align__(256) __half g_B [(size_t)D_DIM * D_DIM];  // fp16(Wp)

// ---------------- helpers ----------------------------------------------------
__device__ __forceinline__ uint32_t smem_u32(const void* p) {
    uint32_t a;
    asm("{ .reg .u64 t; cvta.to.shared.u64 t, %1; cvt.u32.u64 %0, t; }" : "=r"(a) : "l"(p));
    return a;
}
__device__ __forceinline__ void cp16(uint32_t sdst, const void* gsrc) {
    asm volatile("cp.async.cg.shared.global [%0], [%1], 16;" :: "r"(sdst), "l"(gsrc));
}
__device__ __forceinline__ uint32_t sw128(uint32_t o) { return o ^ ((o >> 3) & 0x70); }

__device__ __forceinline__ void ldmatrix_x4(uint32_t* f, uint32_t addr) {
    asm volatile("ldmatrix.sync.aligned.m8n8.x4.shared.b16 {%0,%1,%2,%3}, [%4];"
                 : "=r"(f[0]), "=r"(f[1]), "=r"(f[2]), "=r"(f[3]) : "r"(addr));
}
__device__ __forceinline__ void mma16816(float* c, const uint32_t* a,
                                         uint32_t b0, uint32_t b1) {
    asm volatile(
        "mma.sync.aligned.m16n8k16.row.col.f32.f16.f16.f32 "
        "{%0,%1,%2,%3}, {%4,%5,%6,%7}, {%8,%9}, {%0,%1,%2,%3};"
        : "+f"(c[0]), "+f"(c[1]), "+f"(c[2]), "+f"(c[3])
        : "r"(a[0]), "r"(a[1]), "r"(a[2]), "r"(a[3]), "r"(b0), "r"(b1));
}

// ---------------- fp32 -> fp16 convert (x and Wp in one launch) --------------
__global__ __launch_bounds__(256) void cvt_fp16_kernel(
    const float4* __restrict__ xs, const float4* __restrict__ ws,
    uint2* __restrict__ da, uint2* __restrict__ db, int nx4, int ntot) {
    int i = blockIdx.x * 256 + threadIdx.x;
    if (i >= ntot) return;
    const bool isx = (i < nx4);
    const float4 v = isx ? xs[i] : ws[i - nx4];
    __half2 h0 = __floats2half2_rn(v.x, v.y);
    __half2 h1 = __floats2half2_rn(v.z, v.w);
    uint2 o = make_uint2(*reinterpret_cast<const uint32_t*>(&h0),
                         *reinterpret_cast<const uint32_t*>(&h1));
    if (isx) da[i] = o; else db[i - nx4] = o;
}

// ---------------- HMMA GEMM: g_Ph = fp16((A @ B^T + bp) / 6) -----------------
// CTA 128x128, 128 threads (4 warps 2x2 => 64x64 warp tile), BK=64,
// 3-stage cp.async pipeline (96KB smem -> 2 CTAs/SM), explicit
// double-buffered ldmatrix fragments to overlap smem reads with HMMA.
namespace hg {
constexpr int BM = 128, BN = 128, BK = 64, STAGES = 3;
constexpr int NKT = D_DIM / BK;                 // 32
constexpr int TILE_A = BM * 128;                // 16 KB
constexpr int TILE_B = BN * 128;                // 16 KB
constexpr int SMEM_BYTES = STAGES * (TILE_A + TILE_B) + 1024;  // 99328
}

__global__ __launch_bounds__(128, 2) void gemm_hmma_kernel(const float* __restrict__ bias) {
    using namespace hg;
    extern __shared__ char smem_raw[];
    const uint32_t sbase = (smem_u32(smem_raw) + 1023u) & ~1023u;
    const uint32_t bbase = sbase + STAGES * TILE_A;

    const int tid  = threadIdx.x;
    const int wid  = tid >> 5;
    const int lane = tid & 31;
    const int brow = blockIdx.y * BM;
    const int bcol = blockIdx.x * BN;
    const int wm = wid & 1;
    const int wn = wid >> 1;

    const __half* Ag = g_A + (size_t)brow * D_DIM;
    const __half* Bg = g_B + (size_t)bcol * D_DIM;

    const int lrow = tid >> 3;   // 0..15
    const int lseg = tid & 7;

    auto load_stage = [&](int s, int k0) {
        const uint32_t a_s = sbase + s * TILE_A;
        const uint32_t b_s = bbase + s * TILE_B;
#pragma unroll
        for (int p = 0; p < 8; p++) {
            const int row = lrow + p * 16;
            const uint32_t off = sw128((uint32_t)(row * 128 + lseg * 16));
            const size_t gofs = (size_t)row * D_DIM + k0 + lseg * 8;
            cp16(a_s + off, Ag + gofs);
            cp16(b_s + off, Bg + gofs);
        }
    };

    const int a_r_base = wm * 64 + (lane & 15);
    const int ab_cb    = ((lane >> 4) << 4);
    const int b_r_base = wn * 64 + (lane & 7) + ((lane >> 3) & 1) * 8;

    auto load_frags = [&](uint32_t (&af)[4][4], uint32_t (&bf)[4][4],
                          int s, int kb) {
        const uint32_t a_s = sbase + s * TILE_A;
        const uint32_t b_s = bbase + s * TILE_B;
#pragma unroll
        for (int i = 0; i < 4; i++)
            ldmatrix_x4(af[i], a_s + sw128((uint32_t)((a_r_base + i * 16) * 128 + kb + ab_cb)));
#pragma unroll
        for (int j = 0; j < 4; j++)
            ldmatrix_x4(bf[j], b_s + sw128((uint32_t)((b_r_base + j * 16) * 128 + kb + ab_cb)));
    };

    float acc[4][8][4];
#pragma unroll
    for (int i = 0; i < 4; i++)
#pragma unroll
        for (int j = 0; j < 8; j++)
#pragma unroll
            for (int e = 0; e < 4; e++) acc[i][j][e] = 0.0f;

    auto mma_all = [&](uint32_t (&af)[4][4], uint32_t (&bf)[4][4]) {
#pragma unroll
        for (int i = 0; i < 4; i++)
#pragma unroll
            for (int j = 0; j < 4; j++) {
                mma16816(acc[i][2 * j],     af[i], bf[j][0], bf[j][2]);
                mma16816(acc[i][2 * j + 1], af[i], bf[j][1], bf[j][3]);
            }
    };

    // prologue: stages 0 and 1 in flight
    load_stage(0, 0);
    asm volatile("cp.async.commit_group;" ::: "memory");
    load_stage(1, BK);
    asm volatile("cp.async.commit_group;" ::: "memory");
    asm volatile("cp.async.wait_group 1;" ::: "memory");   // stage 0 ready
    __syncthreads();

    uint32_t af[2][4][4], bf[2][4][4];
    load_frags(af[0], bf[0], 0, 0);

#pragma unroll 1
    for (int kt = 0; kt < NKT; kt++) {
        const int s = kt % STAGES;
        // prefetch stage kt+2 (empty commit keeps group accounting uniform)
        const int pf = kt + 2;
        if (pf < NKT) load_stage(pf % STAGES, pf * BK);
        asm volatile("cp.async.commit_group;" ::: "memory");

#pragma unroll
        for (int kk = 0; kk < BK / 16; kk++) {
            const int cur = kk & 1, nxt = cur ^ 1;
            if (kk < 3) {
                load_frags(af[nxt], bf[nxt], s, (kk + 1) * 32);
            } else if (kt + 1 < NKT) {
                asm volatile("cp.async.wait_group 1;" ::: "memory");  // stage kt+1 ready
                load_frags(af[nxt], bf[nxt], (kt + 1) % STAGES, 0);
            }
            mma_all(af[cur], bf[cur]);
        }
        __syncthreads();   // all warps done reading stage kt before it is overwritten
    }

    // epilogue: fp16 store of (acc + bias) / 6
    const float inv6 = 1.0f / 6.0f;
    const int prow0 = brow + wm * 64 + (lane >> 2);
    const int pcol0 = bcol + wn * 64 + (lane & 3) * 2;
#pragma unroll
    for (int i = 0; i < 4; i++) {
        const size_t r0 = (size_t)(prow0 + i * 16);
#pragma unroll
        for (int j = 0; j < 8; j++) {
            const int c = pcol0 + j * 8;
            const float b0 = bias[c], b1 = bias[c + 1];
            __half2 lo = __floats2half2_rn((acc[i][j][0] + b0) * inv6,
                                           (acc[i][j][1] + b1) * inv6);
            __half2 hi = __floats2half2_rn((acc[i][j][2] + b0) * inv6,
                                           (acc[i][j][3] + b1) * inv6);
            *reinterpret_cast<__half2*>(&g_Ph[r0 * D_DIM + c])       = lo;
            *reinterpret_cast<__half2*>(&g_Ph[(r0 + 8) * D_DIM + c]) = hi;
        }
    }
}

// ---------------- fused chained LayerNorm (vectorized, P in fp16) ------------
__device__ __forceinline__ float2 block_sum2(float a, float b) {
    __shared__ float sm[16];
    const int lane = threadIdx.x & 31;
    const int wid  = threadIdx.x >> 5;
#pragma unroll
    for (int o = 16; o > 0; o >>= 1) {
        a += __shfl_xor_sync(0xffffffffu, a, o);
        b += __shfl_xor_sync(0xffffffffu, b, o);
    }
    __syncthreads();
    if (lane == 0) { sm[wid] = a; sm[8 + wid] = b; }
    __syncthreads();
    float sa = 0.0f, sb = 0.0f;
#pragma unroll
    for (int i = 0; i < 8; i++) { sa += sm[i]; sb += sm[8 + i]; }
    return make_float2(sa, sb);
}

__global__ __launch_bounds__(256) void ln_fuse_kernel(
    const float* __restrict__ x, const float* __restrict__ gamma,
    const float* __restrict__ beta, float* __restrict__ out) {
    const int r   = blockIdx.x;
    const int t   = r & (T_DIM - 1);
    const int tid = threadIdx.x;
    const float invD = 1.0f / (float)D_DIM;
    constexpr int DP = D_DIM / 2;

    const float2*  xr = (const float2*)x + (size_t)r * DP;
    const int p1row   = (t == 0) ? (r + 1) : (r - 1);
    const __half2* p1 = (const __half2*)g_Ph + (size_t)p1row * DP;
    const float2*  g2 = (const float2*)gamma;
    const float2*  b2 = (const float2*)beta;

    float2 v[4];
    float s = 0.0f, sq = 0.0f;
#pragma unroll
    for (int i = 0; i < 4; i++) {
        const int q = i * 256 + tid;
        const float2 xv = xr[q];
        const float2 pv = __half22float2(p1[q]);
        const float a = xv.x + pv.x, b = xv.y + pv.y;
        v[i] = make_float2(a, b);
        s += a + b; sq += a * a + b * b;
    }
    float2 red = block_sum2(s, sq);
    float mean = red.x * invD;
    float var  = red.y * invD - mean * mean;
    float rstd = rsqrtf(var + 1e-5f);

    if (t >= 1 && t <= T_DIM - 2) {
        const __half2* p2 = (const __half2*)g_Ph + (size_t)(r + 1) * DP;
        s = 0.0f; sq = 0.0f;
#pragma unroll
        for (int i = 0; i < 4; i++) {
            const int q = i * 256 + tid;
            const float2 gg = g2[q], bb = b2[q];
            const float2 pv = __half22float2(p2[q]);
            const float a = (v[i].x - mean) * rstd * gg.x + bb.x + pv.x;
            const float b = (v[i].y - mean) * rstd * gg.y + bb.y + pv.y;
            v[i] = make_float2(a, b);
            s += a + b; sq += a * a + b * b;
        }
        red  = block_sum2(s, sq);
        mean = red.x * invD;
        var  = red.y * invD - mean * mean;
        rstd = rsqrtf(var + 1e-5f);
    }

    float2* orow = (float2*)out + (size_t)r * DP;
#pragma unroll
    for (int i = 0; i < 4; i++) {
        const int q = i * 256 + tid;
        const float2 gg = g2[q], bb = b2[q];
        orow[q] = make_float2((v[i].x - mean) * rstd * gg.x + bb.x,
                              (v[i].y - mean) * rstd * gg.y + bb.y);
    }
}

// ---------------- launch ------------------------------------------------------
extern "C" void kernel_launch(void* const* d_in, const int* in_sizes, int n_in,
                              void* d_out, int out_size) {
    const float* x     = (const float*)d_in[0];
    const float* Wp    = (const float*)d_in[5];
    const float* bp    = (const float*)d_in[6];
    const float* gamma = (const float*)d_in[7];
    const float* beta  = (const float*)d_in[8];
    float* out = (float*)d_out;

    static bool attr_set = false;
    if (!attr_set) {
        cudaFuncSetAttribute(gemm_hmma_kernel,
                             cudaFuncAttributeMaxDynamicSharedMemorySize, hg::SMEM_BYTES);
        attr_set = true;
    }

    __half* gA; cudaGetSymbolAddress((void**)&gA, g_A);
    __half* gB; cudaGetSymbolAddress((void**)&gB, g_B);

    const int nx4  = M_DIM * D_DIM / 4;
    const int nw4  = D_DIM * D_DIM / 4;
    const int ntot = nx4 + nw4;
    cvt_fp16_kernel<<<(ntot + 255) / 256, 256>>>(
        (const float4*)x, (const float4*)Wp, (uint2*)gA, (uint2*)gB, nx4, ntot);

    dim3 ggrid(D_DIM / hg::BN, M_DIM / hg::BM);   // (16, 128)
    gemm_hmma_kernel<<<ggrid, 128, hg::SMEM_BYTES>>>(bp);

    ln_fuse_kernel<<<M_DIM, 256>>>(x, gamma, beta, out);
}